// round 15
// baseline (speedup 1.0000x reference)
#include <cuda_runtime.h>
#include <cuda_bf16.h>
#include <math.h>

#define NN 50000
#define EE 800000
#define MT64 ((NN + 63) / 64)
#define NSZ (NN * 64)
#define SCAN_B ((NN + 127) / 128)
typedef unsigned int u32;

// k_step smem: 5 bf16 A tiles (64r x 72 stride; hi 9216 + lo 9216 each) + B
#define AH 0
#define AHS 18432
#define AM 36864
#define AN 55296
#define AG 73728
#define BOF 92160
#define STEP_SMEM 110592
#define PGRID 296
#define TG_SMEM 36864

__device__ __forceinline__ u32 s2u(const void* p) {
    u32 a;
    asm("{ .reg .u64 t; cvta.to.shared.u64 t, %1; cvt.u32.u64 %0, t; }" : "=r"(a) : "l"(p));
    return a;
}
__device__ __forceinline__ void ldsm4(u32& r0, u32& r1, u32& r2, u32& r3, u32 a) {
    asm volatile("ldmatrix.sync.aligned.m8n8.x4.shared.b16 {%0,%1,%2,%3}, [%4];"
                 : "=r"(r0), "=r"(r1), "=r"(r2), "=r"(r3) : "r"(a));
}
__device__ __forceinline__ void ldsm2t(u32& r0, u32& r1, u32 a) {
    asm volatile("ldmatrix.sync.aligned.m8n8.x2.trans.shared.b16 {%0,%1}, [%2];"
                 : "=r"(r0), "=r"(r1) : "r"(a));
}
__device__ __forceinline__ void mma16816(float* c, u32 a0, u32 a1, u32 a2, u32 a3, u32 b0, u32 b1) {
    asm volatile("mma.sync.aligned.m16n8k16.row.col.f32.bf16.bf16.f32 "
                 "{%0,%1,%2,%3}, {%4,%5,%6,%7}, {%8,%9}, {%0,%1,%2,%3};"
                 : "+f"(c[0]), "+f"(c[1]), "+f"(c[2]), "+f"(c[3])
                 : "r"(a0), "r"(a1), "r"(a2), "r"(a3), "r"(b0), "r"(b1));
}
__device__ __forceinline__ void bsplit(float x, unsigned short& hb, unsigned short& lb) {
    __nv_bfloat16 h = __float2bfloat16_rn(x);
    float r = x - __bfloat162float(h);
    __nv_bfloat16 l = __float2bfloat16_rn(r);
    hb = *(unsigned short*)&h;
    lb = *(unsigned short*)&l;
}
__device__ __forceinline__ void store_split4(char* hp, char* lp, float4 v) {
    unsigned short h0, l0, h1, l1, h2, l2, h3, l3;
    bsplit(v.x, h0, l0); bsplit(v.y, h1, l1); bsplit(v.z, h2, l2); bsplit(v.w, h3, l3);
    *(uint2*)hp = make_uint2(((u32)h1 << 16) | h0, ((u32)h3 << 16) | h2);
    *(uint2*)lp = make_uint2(((u32)l1 << 16) | l0, ((u32)l3 << 16) | l2);
}

__device__ float g_stem[(size_t)NN * 192];
__device__ float g_x0[(size_t)NN * 64];
__device__ float g_a[(size_t)NN * 64];
__device__ float g_b[(size_t)NN * 64];
__device__ float g_cell0[(size_t)NN * 256];
__device__ float g_cell1[(size_t)NN * 256];
__device__ float g_sum[(size_t)5 * NSZ];
__device__ float g_nrm[(size_t)5 * NSZ];
__device__ __nv_bfloat16 g_wbk[(size_t)28 * 7 * 8192];
__device__ float g_wmix[14 * 8];
__device__ float g_stats[384];
__device__ float g_part[(size_t)MT64 * 3 * 384];
__device__ float g_invdeg[NN];
__device__ float g_invsqrt[NN];
__device__ float g_ew[EE];
__device__ int g_deg[NN];
__device__ int g_cursor[NN];
__device__ int g_rowptr[NN + 1];
__device__ int g_eid[EE];
__device__ int g_srcs[EE];
__device__ int g_bsum[512];

// ---------------- CSR ----------------
__global__ void k_zero2(int* a, int* b) {
    int i = blockIdx.x * blockDim.x + threadIdx.x;
    if (i < NN) { a[i] = 0; b[i] = 0; }
}
__global__ void k_deg(const int* __restrict__ dst, int* __restrict__ deg) {
    int e = blockIdx.x * blockDim.x + threadIdx.x;
    if (e < EE) atomicAdd(&deg[dst[e]], 1);
}
__global__ void k_degfin(const int* __restrict__ deg, float* __restrict__ invdeg,
                         float* __restrict__ invsqrt) {
    int i = blockIdx.x * blockDim.x + threadIdx.x;
    if (i < NN) {
        float d = (float)max(deg[i], 1);
        invdeg[i] = 1.0f / d;
        invsqrt[i] = rsqrtf(d);
    }
}
__global__ void k_scan1(const int* __restrict__ deg, int* __restrict__ rowptr, int* __restrict__ bsum) {
    __shared__ int s[128];
    int b = blockIdx.x, t = threadIdx.x;
    int i = b * 128 + t;
    int v = (i < NN) ? deg[i] : 0;
    s[t] = v;
    __syncthreads();
    for (int off = 1; off < 128; off <<= 1) {
        int u = (t >= off) ? s[t - off] : 0;
        __syncthreads();
        s[t] += u;
        __syncthreads();
    }
    if (i < NN) rowptr[i] = s[t] - v;
    if (t == 127) bsum[b] = s[127];
}
__global__ void k_scan2(int* __restrict__ bsum) {
    __shared__ int s[512];
    int t = threadIdx.x;
    int v = (t < SCAN_B) ? bsum[t] : 0;
    s[t] = v;
    __syncthreads();
    for (int off = 1; off < 512; off <<= 1) {
        int u = (t >= off) ? s[t - off] : 0;
        __syncthreads();
        s[t] += u;
        __syncthreads();
    }
    if (t < SCAN_B) bsum[t] = s[t] - v;
}
__global__ void k_scan3(int* __restrict__ rowptr, const int* __restrict__ bsum) {
    int i = blockIdx.x * blockDim.x + threadIdx.x;
    if (i < NN) rowptr[i] += bsum[i >> 7];
    if (i == 0) rowptr[NN] = EE;
}
__global__ void k_scatter(const int* __restrict__ dst, const int* __restrict__ rowptr,
                          int* __restrict__ cursor, int* __restrict__ eid) {
    int e = blockIdx.x * blockDim.x + threadIdx.x;
    if (e < EE) {
        int d = dst[e];
        int pos = rowptr[d] + atomicAdd(&cursor[d], 1);
        eid[pos] = e;
    }
}
__global__ void k_sortfill(const int* __restrict__ rowptr, int* __restrict__ eid,
                           const int* __restrict__ src, const float* __restrict__ invsqrt,
                           int* __restrict__ srcs, float* __restrict__ ew) {
    int n = blockIdx.x * blockDim.x + threadIdx.x;
    if (n >= NN) return;
    int r0 = rowptr[n], r1 = rowptr[n + 1];
    for (int i = r0 + 1; i < r1; i++) {
        int key = eid[i];
        int j = i - 1;
        while (j >= r0 && eid[j] > key) { eid[j + 1] = eid[j]; j--; }
        eid[j + 1] = key;
    }
    float isd = invsqrt[n];
    for (int p = r0; p < r1; p++) {
        int e = eid[p];
        int s = src[e];
        srcs[p] = s;
        ew[p] = invsqrt[s] * isd;
    }
}
__global__ void k_softmax(const float* __restrict__ alphas, float* __restrict__ wmix) {
    int r = threadIdx.x;
    if (r >= 14) return;
    float m = -1e30f;
    for (int o = 0; o < 8; o++) m = fmaxf(m, alphas[r * 8 + o]);
    float e[8], s = 0.f;
    for (int o = 0; o < 8; o++) { e[o] = expf(alphas[r * 8 + o] - m); s += e[o]; }
    float inv = 1.0f / s;
    for (int o = 0; o < 8; o++) wmix[r * 8 + o] = e[o] * inv;
}

// 7 bf16-split B panels/slot. A sources: p0:h p1:hs p2:mean p3:norm p4:hs p5:h p6:gmix
__global__ void k_bake(const float* __restrict__ wmix,
                       const float* __restrict__ Wgcn, const float* __restrict__ Wss,
                       const float* __restrict__ Wsn, const float* __restrict__ Wgin,
                       const float* __restrict__ Wgc1, const float* __restrict__ Wgc2,
                       const float* __restrict__ Wmlp, const float* __restrict__ Wgcnii,
                       __nv_bfloat16* __restrict__ wbk) {
    int s = blockIdx.x;
    int ej = s % 14;
    const float* wv = wmix + ej * 8;
    size_t o = (size_t)s * 4096;
    __nv_bfloat16* ob = wbk + (size_t)s * 7 * 8192;
    float w1 = wv[1], w2 = wv[2], w3 = wv[3], w4 = wv[4], w5 = wv[5], w6 = wv[6], w7 = wv[7];
    for (int idx = threadIdx.x; idx < 4096; idx += blockDim.x) {
        int k = idx >> 6, n = idx & 63;
        for (int p = 0; p < 7; p++) {
            float v;
            if (p == 0) v = w3 * Wss[o + idx] + w5 * (Wgc1[o + idx] - Wgc2[o + idx]) + ((k == n) ? w1 : 0.f);
            else if (p == 1) v = w5 * Wgc2[o + idx];
            else if (p == 2) v = w3 * Wsn[o + idx];
            else if (p == 3) v = w2 * Wgcn[o + idx];
            else if (p == 4) v = w4 * Wgin[o + idx];
            else if (p == 5) v = w6 * Wmlp[o + idx];
            else v = w7 * Wgcnii[o + idx];
            unsigned short hb, lb;
            bsplit(v, hb, lb);
            ob[p * 8192 + idx] = *(__nv_bfloat16*)&hb;
            ob[p * 8192 + 4096 + idx] = *(__nv_bfloat16*)&lb;
        }
    }
}

// ---------------- bf16-split tensor GEMM (stem/pre), fused BN column partials ----------------
__global__ __launch_bounds__(128) void k_tgemm(const float* __restrict__ A, int lda,
                                               const float* __restrict__ B, int ldb,
                                               float* __restrict__ C, int ldc, int K,
                                               float* __restrict__ part) {
    extern __shared__ char smc[];
    const u32 sb = s2u(smc);
    const int tid = threadIdx.x, wid = tid >> 5, lane = tid & 31;
    const int wrow = wid * 16;
    const int fg = lane >> 2, tig = lane & 3;
    const int m0 = blockIdx.x * 64, n0 = blockIdx.y * 64;

    float outv[32];
#pragma unroll
    for (int i = 0; i < 32; i++) outv[i] = 0.f;

    for (int kt = 0; kt < K; kt += 64) {
        __syncthreads();
#pragma unroll
        for (int i = 0; i < 8; i++) {
            int idx = tid + i * 128;
            int row = idx >> 4, cg = (idx & 15) * 4;
            int gm = m0 + row;
            float4 av = (gm < NN) ? *(const float4*)(A + (size_t)gm * lda + kt + cg)
                                  : make_float4(0.f, 0.f, 0.f, 0.f);
            int off = row * 144 + cg * 2;
            store_split4(smc + off, smc + 9216 + off, av);
        }
#pragma unroll
        for (int i = 0; i < 8; i++) {
            int idx = tid + i * 128;
            int k = idx >> 4, cg = (idx & 15) * 4;
            float4 bv = *(const float4*)(B + (size_t)(kt + k) * ldb + n0 + cg);
            int off = 18432 + k * 144 + cg * 2;
            store_split4(smc + off, smc + 9216 + off, bv);
        }
        __syncthreads();
#pragma unroll
        for (int q = 0; q < 4; q++) {
            u32 aAddr = sb + (u32)((wrow + (lane & 7) + ((lane >> 3) & 1) * 8) * 144 + q * 32 + (lane >> 4) * 16);
            u32 a0, a1, a2, a3, e0, e1, e2, e3;
            ldsm4(a0, a1, a2, a3, aAddr);
            ldsm4(e0, e1, e2, e3, aAddr + 9216);
            u32 bRow = sb + 18432 + (u32)((q * 16 + (lane & 15)) * 144);
#pragma unroll
            for (int nb = 0; nb < 8; nb++) {
                u32 b0, b1, c0, c1;
                ldsm2t(b0, b1, bRow + nb * 16);
                ldsm2t(c0, c1, bRow + nb * 16 + 9216);
                mma16816(outv + nb * 4, a0, a1, a2, a3, b0, b1);
                mma16816(outv + nb * 4, e0, e1, e2, e3, b0, b1);
                mma16816(outv + nb * 4, a0, a1, a2, a3, c0, c1);
            }
        }
    }
    int r0g = m0 + wrow + fg, r1g = r0g + 8;
    bool v0 = r0g < NN, v1 = r1g < NN;
#pragma unroll
    for (int nb = 0; nb < 8; nb++) {
        int c = n0 + nb * 8 + tig * 2;
        if (v0) *(float2*)(C + (size_t)r0g * ldc + c) = make_float2(outv[nb * 4 + 0], outv[nb * 4 + 1]);
        if (v1) *(float2*)(C + (size_t)r1g * ldc + c) = make_float2(outv[nb * 4 + 2], outv[nb * 4 + 3]);
    }
    // fused BN column partials (deterministic)
    float cs[16], cq[16];
#pragma unroll
    for (int nb = 0; nb < 8; nb++) {
        float a0 = v0 ? outv[nb * 4 + 0] : 0.f, a1 = v0 ? outv[nb * 4 + 1] : 0.f;
        float a2 = v1 ? outv[nb * 4 + 2] : 0.f, a3 = v1 ? outv[nb * 4 + 3] : 0.f;
        cs[nb * 2 + 0] = a0 + a2; cq[nb * 2 + 0] = a0 * a0 + a2 * a2;
        cs[nb * 2 + 1] = a1 + a3; cq[nb * 2 + 1] = a1 * a1 + a3 * a3;
    }
#pragma unroll
    for (int m = 4; m <= 16; m <<= 1)
#pragma unroll
        for (int i = 0; i < 16; i++) {
            cs[i] += __shfl_xor_sync(0xffffffffu, cs[i], m);
            cq[i] += __shfl_xor_sync(0xffffffffu, cq[i], m);
        }
    __syncthreads();
    float* bnS = (float*)smc;
    float* bnQ = (float*)(smc + 1024);
    if (lane < 4) {
#pragma unroll
        for (int nb = 0; nb < 8; nb++) {
            int col = nb * 8 + lane * 2;
            bnS[wid * 64 + col] = cs[nb * 2 + 0];
            bnS[wid * 64 + col + 1] = cs[nb * 2 + 1];
            bnQ[wid * 64 + col] = cq[nb * 2 + 0];
            bnQ[wid * 64 + col + 1] = cq[nb * 2 + 1];
        }
    }
    __syncthreads();
    if (tid < 64) {
        float s = 0.f, q = 0.f;
#pragma unroll
        for (int w = 0; w < 4; w++) { s += bnS[w * 64 + tid]; q += bnQ[w * 64 + tid]; }
        int blkid = blockIdx.x * gridDim.y + blockIdx.y;
        part[(size_t)blkid * 384 + n0 + tid] = s;
        part[(size_t)blkid * 384 + 192 + n0 + tid] = q;
    }
}

__global__ void k_colfin(const float* __restrict__ part, int ny, float* __restrict__ stats) {
    int c = blockIdx.x, t = threadIdx.x;
    int by = c >> 6;
    float s = 0.f, q = 0.f;
    for (int bx = t; bx < MT64; bx += 256) {
        size_t blk = (size_t)(bx * ny + by) * 384;
        s += part[blk + c];
        q += part[blk + 192 + c];
    }
    __shared__ float rs[256], rq[256];
    rs[t] = s; rq[t] = q;
    __syncthreads();
    for (int o = 128; o > 0; o >>= 1) {
        if (t < o) { rs[t] += rs[t + o]; rq[t] += rq[t + o]; }
        __syncthreads();
    }
    if (t == 0) {
        float m = rs[0] / (float)NN;
        float v = rq[0] / (float)NN - m * m;
        stats[c] = m;
        stats[192 + c] = rsqrtf(v + 1e-5f);
    }
}
__global__ void k_bnapply(float* __restrict__ A, int ncols, const float* __restrict__ stats, int dorelu) {
    size_t idx = (size_t)blockIdx.x * blockDim.x + threadIdx.x;
    if (idx >= (size_t)NN * ncols) return;
    int c = (int)(idx % ncols);
    float v = (A[idx] - stats[c]) * stats[192 + c];
    if (dorelu) v = fmaxf(v, 0.f);
    A[idx] = v;
}
__global__ void k_agg(const float* __restrict__ h, int ldh, const int* __restrict__ rowptr,
                      const int* __restrict__ srcs, const float* __restrict__ ew,
                      float* __restrict__ osum, float* __restrict__ onrm) {
    int warp = (blockIdx.x * blockDim.x + threadIdx.x) >> 5;
    if (warp >= NN) return;
    int lane = threadIdx.x & 31;
    int r0 = rowptr[warp], r1 = rowptr[warp + 1];
    float2 s = make_float2(0.f, 0.f), nrm = make_float2(0.f, 0.f);
    for (int p = r0; p < r1; p++) {
        int si = srcs[p];
        float w = ew[p];
        float2 v = *(const float2*)&h[(size_t)si * ldh + lane * 2];
        s.x += v.x; s.y += v.y;
        nrm.x += w * v.x; nrm.y += w * v.y;
    }
    *(float2*)&osum[(size_t)warp * 64 + lane * 2] = s;
    *(float2*)&onrm[(size_t)warp * 64 + lane * 2] = nrm;
}
__global__ void k_agg2(const float* __restrict__ h0, int l0, const float* __restrict__ h1, int l1,
                       const int* __restrict__ rowptr, const int* __restrict__ srcs,
                       const float* __restrict__ ew,
                       float* __restrict__ sums, float* __restrict__ nrms) {
    int warp = (blockIdx.x * blockDim.x + threadIdx.x) >> 5;
    if (warp >= NN) return;
    int lane = threadIdx.x & 31;
    int r0 = rowptr[warp], r1 = rowptr[warp + 1];
    float2 s0 = make_float2(0.f, 0.f), n0 = make_float2(0.f, 0.f);
    float2 s1 = make_float2(0.f, 0.f), n1 = make_float2(0.f, 0.f);
    for (int p = r0; p < r1; p++) {
        int si = srcs[p];
        float w = ew[p];
        float2 v0 = *(const float2*)&h0[(size_t)si * l0 + lane * 2];
        float2 v1 = *(const float2*)&h1[(size_t)si * l1 + lane * 2];
        s0.x += v0.x; s0.y += v0.y; n0.x += w * v0.x; n0.y += w * v0.y;
        s1.x += v1.x; s1.y += v1.y; n1.x += w * v1.x; n1.y += w * v1.y;
    }
    size_t o = (size_t)warp * 64 + lane * 2;
    *(float2*)&sums[o] = s0;
    *(float2*)&nrms[o] = n0;
    *(float2*)&sums[NSZ + o] = s1;
    *(float2*)&nrms[NSZ + o] = n1;
}

// ---------------- persistent raw-mma bf16-split step kernel: 7 panels, 5 A tiles ----------------
__global__ __launch_bounds__(128, 2) void k_step(
    const float* __restrict__ h0p, const float* __restrict__ h1p, const float* __restrict__ h2p,
    const float* __restrict__ h3p, const float* __restrict__ h4p,
    int l0, int l1, int l2, int l3, int l4,
    const float* __restrict__ sums, const float* __restrict__ nrms,
    const float* __restrict__ x0, const float* __restrict__ invdeg,
    const __nv_bfloat16* __restrict__ wbase, int nst, float* __restrict__ outp) {
    extern __shared__ char smc[];
    const u32 sb = s2u(smc);
    const int tid = threadIdx.x, wid = tid >> 5, lane = tid & 31;
    const int wrow = wid * 16;
    const int fg = lane >> 2, tig = lane & 3;
    const int pa[7] = {AH, AHS, AM, AN, AHS, AH, AG};
    const int prelu[7] = {0, 0, 0, 1, 1, 1, 1};

    for (int m0 = blockIdx.x * 64; m0 < NN; m0 += gridDim.x * 64) {
        float outv[32];
#pragma unroll
        for (int i = 0; i < 32; i++) outv[i] = 0.f;
        uint4 pf[8];
        {
            const uint4* s = (const uint4*)wbase;
#pragma unroll
            for (int i = 0; i < 8; i++) pf[i] = s[tid + i * 128];
        }

        for (int j = 0; j < nst; j++) {
            const float* h = (j == 0) ? h0p : (j == 1) ? h1p : (j == 2) ? h2p : (j == 3) ? h3p : h4p;
            int ldh = (j == 0) ? l0 : (j == 1) ? l1 : (j == 2) ? l2 : (j == 3) ? l3 : l4;
            const float* ssum = sums + (size_t)j * NSZ;
            const float* snrm = nrms + (size_t)j * NSZ;
            const __nv_bfloat16* wslot = wbase + (size_t)j * 7 * 8192;

            __syncthreads();
#pragma unroll
            for (int i = 0; i < 8; i++) {
                int idx = tid + i * 128;
                int row = idx >> 4, cg = (idx & 15) * 4;
                int gm = m0 + row;
                float4 z = make_float4(0.f, 0.f, 0.f, 0.f);
                float4 hv = z, sv = z, nv = z, xv = z;
                float idg = 0.f;
                if (gm < NN) {
                    hv = *(const float4*)(h + (size_t)gm * ldh + cg);
                    sv = *(const float4*)(ssum + (size_t)gm * 64 + cg);
                    nv = *(const float4*)(snrm + (size_t)gm * 64 + cg);
                    xv = *(const float4*)(x0 + (size_t)gm * 64 + cg);
                    idg = invdeg[gm];
                }
                float4 hs = make_float4(hv.x + sv.x, hv.y + sv.y, hv.z + sv.z, hv.w + sv.w);
                float4 mv = make_float4(sv.x * idg, sv.y * idg, sv.z * idg, sv.w * idg);
                float4 gv = make_float4(0.9f * nv.x + 0.1f * xv.x, 0.9f * nv.y + 0.1f * xv.y,
                                        0.9f * nv.z + 0.1f * xv.z, 0.9f * nv.w + 0.1f * xv.w);
                int off = row * 144 + cg * 2;
                store_split4(smc + AH + off, smc + AH + 9216 + off, hv);
                store_split4(smc + AHS + off, smc + AHS + 9216 + off, hs);
                store_split4(smc + AM + off, smc + AM + 9216 + off, mv);
                store_split4(smc + AN + off, smc + AN + 9216 + off, nv);
                store_split4(smc + AG + off, smc + AG + 9216 + off, gv);
            }

            for (int p = 0; p < 7; p++) {
                __syncthreads();
#pragma unroll
                for (int i = 0; i < 8; i++) {
                    int u = tid + i * 128;
                    int r = u >> 3, c = u & 7;
                    int dst = BOF + ((r < 64) ? (r * 144 + c * 16) : (9216 + (r - 64) * 144 + c * 16));
                    *(uint4*)(smc + dst) = pf[i];
                }
                __syncthreads();
                if (p < 6 || j + 1 < nst) {
                    const uint4* s = (const uint4*)(wslot + (size_t)(p + 1) * 8192);
#pragma unroll
                    for (int i = 0; i < 8; i++) pf[i] = s[tid + i * 128];
                }
                float tc[32];
                float* dst = prelu[p] ? tc : outv;
                if (prelu[p]) {
#pragma unroll
                    for (int i = 0; i < 32; i++) tc[i] = 0.f;
                }
                const u32 At = sb + pa[p];
#pragma unroll
                for (int q = 0; q < 4; q++) {
                    u32 aAddr = At + (u32)((wrow + (lane & 7) + ((lane >> 3) & 1) * 8) * 144 + q * 32 + (lane >> 4) * 16);
                    u32 a0, a1, a2, a3, e0, e1, e2, e3;
                    ldsm4(a0, a1, a2, a3, aAddr);
                    ldsm4(e0, e1, e2, e3, aAddr + 9216);
                    u32 bRow = sb + BOF + (u32)((q * 16 + (lane & 15)) * 144);
#pragma unroll
                    for (int nb = 0; nb < 8; nb++) {
                        u32 b0, b1, c0, c1;
                        ldsm2t(b0, b1, bRow + nb * 16);
                        ldsm2t(c0, c1, bRow + nb * 16 + 9216);
                        mma16816(dst + nb * 4, a0, a1, a2, a3, b0, b1);
                        mma16816(dst + nb * 4, e0, e1, e2, e3, b0, b1);
                        mma16816(dst + nb * 4, a0, a1, a2, a3, c0, c1);
                    }
                }
                if (prelu[p]) {
#pragma unroll
                    for (int i = 0; i < 32; i++) outv[i] += fmaxf(tc[i], 0.f);
                }
            }
        }
        int r0g = m0 + wrow + fg, r1g = r0g + 8;
#pragma unroll
        for (int nb = 0; nb < 8; nb++) {
            int c = nb * 8 + tig * 2;
            if (r0g < NN)
                *(float2*)(outp + (size_t)r0g * 256 + c) = make_float2(outv[nb * 4 + 0], outv[nb * 4 + 1]);
            if (r1g < NN)
                *(float2*)(outp + (size_t)r1g * 256 + c) = make_float2(outv[nb * 4 + 2], outv[nb * 4 + 3]);
        }
    }
}

__global__ void k_cls(const float* __restrict__ s1, const float* __restrict__ W,
                      const float* __restrict__ b, float* __restrict__ out) {
    int n = blockIdx.x;
    __shared__ float row[256];
    __shared__ float red[64];
    int tid = threadIdx.x;
    float ls = 0.f;
#pragma unroll
    for (int i = 0; i < 4; i++) {
        float v = s1[(size_t)n * 256 + tid + i * 64];
        row[tid + i * 64] = v;
        ls += v;
    }
    red[tid] = ls;
    __syncthreads();
    for (int off = 32; off > 0; off >>= 1) {
        if (tid < off) red[tid] += red[tid + off];
        __syncthreads();
    }
    float pooled = red[0] * (1.0f / 256.0f);
    if (tid < 40) {
        float acc = b[tid] + pooled * W[tid];
#pragma unroll 8
        for (int k = 0; k < 256; k++) acc += row[k] * W[(1 + k) * 40 + tid];
        out[(size_t)n * 40 + tid] = acc;
    }
}

static void bnrun(float* buf, int ncols, int ny, int dorelu, float* part, float* stats) {
    k_colfin<<<ncols, 256>>>(part, ny, stats);
    size_t total = (size_t)NN * ncols;
    k_bnapply<<<(int)((total + 255) / 256), 256>>>(buf, ncols, stats, dorelu);
}

extern "C" void kernel_launch(void* const* d_in, const int* in_sizes, int n_in,
                              void* d_out, int out_size) {
    const float* x = (const float*)d_in[0];
    const int* ei = (const int*)d_in[1];
    const float* alphas = (const float*)d_in[2];
    const float* stemW = (const float*)d_in[3];
    const float* preW = (const float*)d_in[4];
    const float* p0W0 = (const float*)d_in[5];
    const float* p1W0 = (const float*)d_in[6];
    const float* p0W1 = (const float*)d_in[7];
    const float* p1W1 = (const float*)d_in[8];
    const float* Wgcn = (const float*)d_in[9];
    const float* Wss = (const float*)d_in[10];
    const float* Wsn = (const float*)d_in[11];
    const float* Wgin = (const float*)d_in[12];
    const float* Wgc1 = (const float*)d_in[13];
    const float* Wgc2 = (const float*)d_in[14];
    const float* Wmlp = (const float*)d_in[15];
    const float* Wgcnii = (const float*)d_in[16];
    const float* clsW = (const float*)d_in[17];
    const float* clsb = (const float*)d_in[18];
    float* out = (float*)d_out;
    const int* srcI = ei;
    const int* dstI = ei + EE;

    float *stem, *x0p, *ap, *bp, *c0, *c1, *sums, *nrms, *wmix, *stats, *part;
    float *invdeg, *invsqrt, *ew;
    __nv_bfloat16* wbk;
    int *deg, *cursor, *rowptr, *eid, *srcs, *bsum;
    cudaGetSymbolAddress((void**)&stem, g_stem);
    cudaGetSymbolAddress((void**)&x0p, g_x0);
    cudaGetSymbolAddress((void**)&ap, g_a);
    cudaGetSymbolAddress((void**)&bp, g_b);
    cudaGetSymbolAddress((void**)&c0, g_cell0);
    cudaGetSymbolAddress((void**)&c1, g_cell1);
    cudaGetSymbolAddress((void**)&sums, g_sum);
    cudaGetSymbolAddress((void**)&nrms, g_nrm);
    cudaGetSymbolAddress((void**)&wbk, g_wbk);
    cudaGetSymbolAddress((void**)&wmix, g_wmix);
    cudaGetSymbolAddress((void**)&stats, g_stats);
    cudaGetSymbolAddress((void**)&part, g_part);
    cudaGetSymbolAddress((void**)&invdeg, g_invdeg);
    cudaGetSymbolAddress((void**)&invsqrt, g_invsqrt);
    cudaGetSymbolAddress((void**)&ew, g_ew);
    cudaGetSymbolAddress((void**)&deg, g_deg);
    cudaGetSymbolAddress((void**)&cursor, g_cursor);
    cudaGetSymbolAddress((void**)&rowptr, g_rowptr);
    cudaGetSymbolAddress((void**)&eid, g_eid);
    cudaGetSymbolAddress((void**)&srcs, g_srcs);
    cudaGetSymbolAddress((void**)&bsum, g_bsum);

    cudaFuncSetAttribute(k_step, cudaFuncAttributeMaxDynamicSharedMemorySize, STEP_SMEM);

    k_zero2<<<(NN + 255) / 256, 256>>>(deg, cursor);
    k_deg<<<(EE + 255) / 256, 256>>>(dstI, deg);
    k_degfin<<<(NN + 255) / 256, 256>>>(deg, invdeg, invsqrt);
    k_scan1<<<SCAN_B, 128>>>(deg, rowptr, bsum);
    k_scan2<<<1, 512>>>(bsum);
    k_scan3<<<(NN + 255) / 256, 256>>>(rowptr, bsum);
    k_scatter<<<(EE + 255) / 256, 256>>>(dstI, rowptr, cursor, eid);
    k_sortfill<<<(NN + 127) / 128, 128>>>(rowptr, eid, srcI, invsqrt, srcs, ew);

    k_softmax<<<1, 16>>>(alphas, wmix);
    k_bake<<<28, 256>>>(wmix, Wgcn, Wss, Wsn, Wgin, Wgc1, Wgc2, Wmlp, Wgcnii, wbk);

    k_tgemm<<<dim3(MT64, 3), 128, TG_SMEM>>>(x, 128, stemW, 192, stem, 192, 128, part);
    bnrun(stem, 192, 3, 0, part, stats);
    k_tgemm<<<dim3(MT64, 1), 128, TG_SMEM>>>(x, 128, preW, 64, x0p, 64, 128, part);
    bnrun(x0p, 64, 1, 1, part, stats);

    const int aggBlocks = (NN * 32 + 255) / 256;
    for (int ci = 0; ci < 2; ci++) {
        const float* s0 = stem; int k0 = 192;
        const float* s1 = (ci == 0) ? stem : c0;
        int k1 = (ci == 0) ? 192 : 256;
        const float* pW0 = (ci == 0) ? p0W0 : p0W1;
        const float* pW1 = (ci == 0) ? p1W0 : p1W1;
        float* cell = (ci == 0) ? c0 : c1;

        k_tgemm<<<dim3(MT64, 1), 128, TG_SMEM>>>(s0, k0, pW0, 64, ap, 64, k0, part);
        bnrun(ap, 64, 1, 1, part, stats);
        k_tgemm<<<dim3(MT64, 1), 128, TG_SMEM>>>(s1, k1, pW1, 64, bp, 64, k1, part);
        bnrun(bp, 64, 1, 1, part, stats);

        const float* sp[5] = {ap, bp, cell, cell + 64, cell + 128};
        const int sl[5] = {64, 64, 256, 256, 256};
        k_agg2<<<aggBlocks, 256>>>(sp[0], sl[0], sp[1], sl[1], rowptr, srcs, ew, sums, nrms);

        int ej0 = 0;
        for (int t = 0; t < 4; t++) {
            const __nv_bfloat16* wb = wbk + (size_t)(ci * 14 + ej0) * 7 * 8192;
            k_step<<<PGRID, 128, STEP_SMEM>>>(sp[0], sp[1], sp[2], sp[3], sp[4],
                                              sl[0], sl[1], sl[2], sl[3], sl[4],
                                              sums, nrms, x0p, invdeg, wb, t + 2, cell + t * 64);
            ej0 += t + 2;
            if (t < 3) {
                int ns = t + 2;
                k_agg<<<aggBlocks, 256>>>(sp[ns], sl[ns], rowptr, srcs, ew,
                                          sums + (size_t)ns * NSZ, nrms + (size_t)ns * NSZ);
            }
        }
    }
    k_cls<<<NN, 64>>>(c1, clsW, clsb, out);
}

// round 16
// speedup vs baseline: 1.3474x; 1.3474x over previous
#include <cuda_runtime.h>
#include <cuda_bf16.h>
#include <math.h>

#define NN 50000
#define EE 800000
#define MT64 ((NN + 63) / 64)
#define NSZ (NN * 64)
#define SCAN_B ((NN + 127) / 128)
#define TS 4352
typedef unsigned int u32;

// k_step smem: 5 bf16 A tiles (64r x 72 stride; hi 9216 + lo 9216 each) + B
#define AH 0
#define AHS 18432
#define AM 36864
#define AN 55296
#define AG 73728
#define BOF 92160
#define STEP_SMEM 110592
#define PGRID 296

__device__ __forceinline__ u32 s2u(const void* p) {
    u32 a;
    asm("{ .reg .u64 t; cvta.to.shared.u64 t, %1; cvt.u32.u64 %0, t; }" : "=r"(a) : "l"(p));
    return a;
}
__device__ __forceinline__ void ldsm4(u32& r0, u32& r1, u32& r2, u32& r3, u32 a) {
    asm volatile("ldmatrix.sync.aligned.m8n8.x4.shared.b16 {%0,%1,%2,%3}, [%4];"
                 : "=r"(r0), "=r"(r1), "=r"(r2), "=r"(r3) : "r"(a));
}
__device__ __forceinline__ void ldsm2t(u32& r0, u32& r1, u32 a) {
    asm volatile("ldmatrix.sync.aligned.m8n8.x2.trans.shared.b16 {%0,%1}, [%2];"
                 : "=r"(r0), "=r"(r1) : "r"(a));
}
__device__ __forceinline__ void mma16816(float* c, u32 a0, u32 a1, u32 a2, u32 a3, u32 b0, u32 b1) {
    asm volatile("mma.sync.aligned.m16n8k16.row.col.f32.bf16.bf16.f32 "
                 "{%0,%1,%2,%3}, {%4,%5,%6,%7}, {%8,%9}, {%0,%1,%2,%3};"
                 : "+f"(c[0]), "+f"(c[1]), "+f"(c[2]), "+f"(c[3])
                 : "r"(a0), "r"(a1), "r"(a2), "r"(a3), "r"(b0), "r"(b1));
}
__device__ __forceinline__ void bsplit(float x, unsigned short& hb, unsigned short& lb) {
    __nv_bfloat16 h = __float2bfloat16_rn(x);
    float r = x - __bfloat162float(h);
    __nv_bfloat16 l = __float2bfloat16_rn(r);
    hb = *(unsigned short*)&h;
    lb = *(unsigned short*)&l;
}
__device__ __forceinline__ void store_split4(char* hp, char* lp, float4 v) {
    unsigned short h0, l0, h1, l1, h2, l2, h3, l3;
    bsplit(v.x, h0, l0); bsplit(v.y, h1, l1); bsplit(v.z, h2, l2); bsplit(v.w, h3, l3);
    *(uint2*)hp = make_uint2(((u32)h1 << 16) | h0, ((u32)h3 << 16) | h2);
    *(uint2*)lp = make_uint2(((u32)l1 << 16) | l0, ((u32)l3 << 16) | l2);
}

__device__ float g_stem[(size_t)NN * 192];
__device__ float g_x0[(size_t)NN * 64];
__device__ float g_a[(size_t)NN * 64];
__device__ float g_b[(size_t)NN * 64];
__device__ float g_cell0[(size_t)NN * 256];
__device__ float g_cell1[(size_t)NN * 256];
__device__ float g_sum[(size_t)5 * NSZ];
__device__ float g_nrm[(size_t)5 * NSZ];
__device__ __nv_bfloat16 g_wbk[(size_t)28 * 7 * 8192];  // 7 panels: hi[64][64]+lo[64][64]
__device__ float g_wmix[14 * 8];
__device__ float g_stats[384];
__device__ float g_part[(size_t)MT64 * 3 * 384];
__device__ float g_invdeg[NN];
__device__ float g_invsqrt[NN];
__device__ float g_ew[EE];
__device__ int g_deg[NN];
__device__ int g_cursor[NN];
__device__ int g_rowptr[NN + 1];
__device__ int g_eid[EE];
__device__ int g_srcs[EE];
__device__ int g_bsum[512];

// ---------------- CSR ----------------
__global__ void k_zero2(int* a, int* b) {
    int i = blockIdx.x * blockDim.x + threadIdx.x;
    if (i < NN) { a[i] = 0; b[i] = 0; }
}
__global__ void k_deg(const int* __restrict__ dst, int* __restrict__ deg) {
    int e = blockIdx.x * blockDim.x + threadIdx.x;
    if (e < EE) atomicAdd(&deg[dst[e]], 1);
}
__global__ void k_degfin(const int* __restrict__ deg, float* __restrict__ invdeg,
                         float* __restrict__ invsqrt) {
    int i = blockIdx.x * blockDim.x + threadIdx.x;
    if (i < NN) {
        float d = (float)max(deg[i], 1);
        invdeg[i] = 1.0f / d;
        invsqrt[i] = rsqrtf(d);
    }
}
__global__ void k_scan1(const int* __restrict__ deg, int* __restrict__ rowptr, int* __restrict__ bsum) {
    __shared__ int s[128];
    int b = blockIdx.x, t = threadIdx.x;
    int i = b * 128 + t;
    int v = (i < NN) ? deg[i] : 0;
    s[t] = v;
    __syncthreads();
    for (int off = 1; off < 128; off <<= 1) {
        int u = (t >= off) ? s[t - off] : 0;
        __syncthreads();
        s[t] += u;
        __syncthreads();
    }
    if (i < NN) rowptr[i] = s[t] - v;
    if (t == 127) bsum[b] = s[127];
}
__global__ void k_scan2(int* __restrict__ bsum) {
    __shared__ int s[512];
    int t = threadIdx.x;
    int v = (t < SCAN_B) ? bsum[t] : 0;
    s[t] = v;
    __syncthreads();
    for (int off = 1; off < 512; off <<= 1) {
        int u = (t >= off) ? s[t - off] : 0;
        __syncthreads();
        s[t] += u;
        __syncthreads();
    }
    if (t < SCAN_B) bsum[t] = s[t] - v;
}
__global__ void k_scan3(int* __restrict__ rowptr, const int* __restrict__ bsum) {
    int i = blockIdx.x * blockDim.x + threadIdx.x;
    if (i < NN) rowptr[i] += bsum[i >> 7];
    if (i == 0) rowptr[NN] = EE;
}
__global__ void k_scatter(const int* __restrict__ dst, const int* __restrict__ rowptr,
                          int* __restrict__ cursor, int* __restrict__ eid) {
    int e = blockIdx.x * blockDim.x + threadIdx.x;
    if (e < EE) {
        int d = dst[e];
        int pos = rowptr[d] + atomicAdd(&cursor[d], 1);
        eid[pos] = e;
    }
}
__global__ void k_sortfill(const int* __restrict__ rowptr, int* __restrict__ eid,
                           const int* __restrict__ src, const float* __restrict__ invsqrt,
                           int* __restrict__ srcs, float* __restrict__ ew) {
    int n = blockIdx.x * blockDim.x + threadIdx.x;
    if (n >= NN) return;
    int r0 = rowptr[n], r1 = rowptr[n + 1];
    for (int i = r0 + 1; i < r1; i++) {
        int key = eid[i];
        int j = i - 1;
        while (j >= r0 && eid[j] > key) { eid[j + 1] = eid[j]; j--; }
        eid[j + 1] = key;
    }
    float isd = invsqrt[n];
    for (int p = r0; p < r1; p++) {
        int e = eid[p];
        int s = src[e];
        srcs[p] = s;
        ew[p] = invsqrt[s] * isd;
    }
}
__global__ void k_softmax(const float* __restrict__ alphas, float* __restrict__ wmix) {
    int r = threadIdx.x;
    if (r >= 14) return;
    float m = -1e30f;
    for (int o = 0; o < 8; o++) m = fmaxf(m, alphas[r * 8 + o]);
    float e[8], s = 0.f;
    for (int o = 0; o < 8; o++) { e[o] = expf(alphas[r * 8 + o] - m); s += e[o]; }
    float inv = 1.0f / s;
    for (int o = 0; o < 8; o++) wmix[r * 8 + o] = e[o] * inv;
}

// 7 bf16-split B panels/slot. A sources: p0:h p1:hs p2:mean p3:norm p4:hs p5:h p6:gmix
__global__ void k_bake(const float* __restrict__ wmix,
                       const float* __restrict__ Wgcn, const float* __restrict__ Wss,
                       const float* __restrict__ Wsn, const float* __restrict__ Wgin,
                       const float* __restrict__ Wgc1, const float* __restrict__ Wgc2,
                       const float* __restrict__ Wmlp, const float* __restrict__ Wgcnii,
                       __nv_bfloat16* __restrict__ wbk) {
    int s = blockIdx.x;
    int ej = s % 14;
    const float* wv = wmix + ej * 8;
    size_t o = (size_t)s * 4096;
    __nv_bfloat16* ob = wbk + (size_t)s * 7 * 8192;
    float w1 = wv[1], w2 = wv[2], w3 = wv[3], w4 = wv[4], w5 = wv[5], w6 = wv[6], w7 = wv[7];
    for (int idx = threadIdx.x; idx < 4096; idx += blockDim.x) {
        int k = idx >> 6, n = idx & 63;
        for (int p = 0; p < 7; p++) {
            float v;
            if (p == 0) v = w3 * Wss[o + idx] + w5 * (Wgc1[o + idx] - Wgc2[o + idx]) + ((k == n) ? w1 : 0.f);
            else if (p == 1) v = w5 * Wgc2[o + idx];
            else if (p == 2) v = w3 * Wsn[o + idx];
            else if (p == 3) v = w2 * Wgcn[o + idx];
            else if (p == 4) v = w4 * Wgin[o + idx];
            else if (p == 5) v = w6 * Wmlp[o + idx];
            else v = w7 * Wgcnii[o + idx];
            unsigned short hb, lb;
            bsplit(v, hb, lb);
            ob[p * 8192 + idx] = *(__nv_bfloat16*)&hb;
            ob[p * 8192 + 4096 + idx] = *(__nv_bfloat16*)&lb;
        }
    }
}

// ---------------- fp32 tiled GEMM with fused BN column partials ----------------
__global__ __launch_bounds__(256) void k_gemm(const float* __restrict__ A, int lda,
                                              const float* __restrict__ B, int ldb,
                                              float* __restrict__ C, int K,
                                              float* __restrict__ part) {
    __shared__ float As[TS];
    __shared__ float Bs[TS];
    const int tid = threadIdx.x;
    const int m0 = blockIdx.x * 64;
    const int n0b = blockIdx.y * 64;
    const int tx = tid & 15, ty = tid >> 4;
    const int n0 = tx * 4, mm0 = ty * 4;
    float acc[16];
#pragma unroll
    for (int i = 0; i < 16; i++) acc[i] = 0.f;
    for (int kt = 0; kt < K; kt += 64) {
        __syncthreads();
#pragma unroll
        for (int i = 0; i < 16; i++) {
            int idx = tid + i * 256;
            int m = idx >> 6, k = idx & 63;
            int gm = m0 + m;
            As[k * 68 + m] = (gm < NN) ? A[(size_t)gm * lda + kt + k] : 0.f;
            Bs[(idx >> 6) * 68 + (idx & 63)] = B[(size_t)(kt + (idx >> 6)) * ldb + n0b + (idx & 63)];
        }
        __syncthreads();
#pragma unroll 16
        for (int k = 0; k < 64; k++) {
            float4 a4 = *(const float4*)&As[k * 68 + mm0];
            float4 b4 = *(const float4*)&Bs[k * 68 + n0];
            acc[0] += a4.x * b4.x; acc[1] += a4.x * b4.y; acc[2] += a4.x * b4.z; acc[3] += a4.x * b4.w;
            acc[4] += a4.y * b4.x; acc[5] += a4.y * b4.y; acc[6] += a4.y * b4.z; acc[7] += a4.y * b4.w;
            acc[8] += a4.z * b4.x; acc[9] += a4.z * b4.y; acc[10] += a4.z * b4.z; acc[11] += a4.z * b4.w;
            acc[12] += a4.w * b4.x; acc[13] += a4.w * b4.y; acc[14] += a4.w * b4.z; acc[15] += a4.w * b4.w;
        }
    }
#pragma unroll
    for (int r = 0; r < 4; r++) {
        int gm = m0 + mm0 + r;
        if (gm < NN)
            *(float4*)&C[(size_t)gm * ldb + n0b + n0] =
                make_float4(acc[r * 4], acc[r * 4 + 1], acc[r * 4 + 2], acc[r * 4 + 3]);
    }
    __syncthreads();
#pragma unroll
    for (int c = 0; c < 4; c++) {
        float s = 0.f, q = 0.f;
#pragma unroll
        for (int r = 0; r < 4; r++) {
            if (m0 + mm0 + r < NN) { float v = acc[r * 4 + c]; s += v; q += v * v; }
        }
        As[ty * 64 + n0 + c] = s;
        Bs[ty * 64 + n0 + c] = q;
    }
    __syncthreads();
    if (ty == 0) {
        int blkid = blockIdx.x * gridDim.y + blockIdx.y;
#pragma unroll
        for (int c = 0; c < 4; c++) {
            float s = 0.f, q = 0.f;
#pragma unroll
            for (int t = 0; t < 16; t++) { s += As[t * 64 + n0 + c]; q += Bs[t * 64 + n0 + c]; }
            part[(size_t)blkid * 384 + n0b + n0 + c] = s;
            part[(size_t)blkid * 384 + 192 + n0b + n0 + c] = q;
        }
    }
}

__global__ void k_colfin(const float* __restrict__ part, int ny, float* __restrict__ stats) {
    int c = blockIdx.x, t = threadIdx.x;
    int by = c >> 6;
    float s = 0.f, q = 0.f;
    for (int bx = t; bx < MT64; bx += 256) {
        size_t blk = (size_t)(bx * ny + by) * 384;
        s += part[blk + c];
        q += part[blk + 192 + c];
    }
    __shared__ float rs[256], rq[256];
    rs[t] = s; rq[t] = q;
    __syncthreads();
    for (int o = 128; o > 0; o >>= 1) {
        if (t < o) { rs[t] += rs[t + o]; rq[t] += rq[t + o]; }
        __syncthreads();
    }
    if (t == 0) {
        float m = rs[0] / (float)NN;
        float v = rq[0] / (float)NN - m * m;
        stats[c] = m;
        stats[192 + c] = rsqrtf(v + 1e-5f);
    }
}
__global__ void k_bnapply(float* __restrict__ A, int ncols, const float* __restrict__ stats, int dorelu) {
    size_t idx = (size_t)blockIdx.x * blockDim.x + threadIdx.x;
    if (idx >= (size_t)NN * ncols) return;
    int c = (int)(idx % ncols);
    float v = (A[idx] - stats[c]) * stats[192 + c];
    if (dorelu) v = fmaxf(v, 0.f);
    A[idx] = v;
}
__global__ void k_agg(const float* __restrict__ h, int ldh, const int* __restrict__ rowptr,
                      const int* __restrict__ srcs, const float* __restrict__ ew,
                      float* __restrict__ osum, float* __restrict__ onrm) {
    int warp = (blockIdx.x * blockDim.x + threadIdx.x) >> 5;
    if (warp >= NN) return;
    int lane = threadIdx.x & 31;
    int r0 = rowptr[warp], r1 = rowptr[warp + 1];
    float2 s = make_float2(0.f, 0.f), nrm = make_float2(0.f, 0.f);
    for (int p = r0; p < r1; p++) {
        int si = srcs[p];
        float w = ew[p];
        float2 v = *(const float2*)&h[(size_t)si * ldh + lane * 2];
        s.x += v.x; s.y += v.y;
        nrm.x += w * v.x; nrm.y += w * v.y;
    }
    *(float2*)&osum[(size_t)warp * 64 + lane * 2] = s;
    *(float2*)&onrm[(size_t)warp * 64 + lane * 2] = nrm;
}
__global__ void k_agg2(const float* __restrict__ h0, int l0, const float* __restrict__ h1, int l1,
                       const int* __restrict__ rowptr, const int* __restrict__ srcs,
                       const float* __restrict__ ew,
                       float* __restrict__ sums, float* __restrict__ nrms) {
    int warp = (blockIdx.x * blockDim.x + threadIdx.x) >> 5;
    if (warp >= NN) return;
    int lane = threadIdx.x & 31;
    int r0 = rowptr[warp], r1 = rowptr[warp + 1];
    float2 s0 = make_float2(0.f, 0.f), n0 = make_float2(0.f, 0.f);
    float2 s1 = make_float2(0.f, 0.f), n1 = make_float2(0.f, 0.f);
    for (int p = r0; p < r1; p++) {
        int si = srcs[p];
        float w = ew[p];
        float2 v0 = *(const float2*)&h0[(size_t)si * l0 + lane * 2];
        float2 v1 = *(const float2*)&h1[(size_t)si * l1 + lane * 2];
        s0.x += v0.x; s0.y += v0.y; n0.x += w * v0.x; n0.y += w * v0.y;
        s1.x += v1.x; s1.y += v1.y; n1.x += w * v1.x; n1.y += w * v1.y;
    }
    size_t o = (size_t)warp * 64 + lane * 2;
    *(float2*)&sums[o] = s0;
    *(float2*)&nrms[o] = n0;
    *(float2*)&sums[NSZ + o] = s1;
    *(float2*)&nrms[NSZ + o] = n1;
}

// ---------------- persistent raw-mma bf16-split step kernel: 7 panels, 5 A tiles ----------------
__global__ __launch_bounds__(128, 2) void k_step(
    const float* __restrict__ h0p, const float* __restrict__ h1p, const float* __restrict__ h2p,
    const float* __restrict__ h3p, const float* __restrict__ h4p,
    int l0, int l1, int l2, int l3, int l4,
    const float* __restrict__ sums, const float* __restrict__ nrms,
    const float* __restrict__ x0, const float* __restrict__ invdeg,
    const __nv_bfloat16* __restrict__ wbase, int nst, float* __restrict__ outp) {
    extern __shared__ char smc[];
    const u32 sb = s2u(smc);
    const int tid = threadIdx.x, wid = tid >> 5, lane = tid & 31;
    const int wrow = wid * 16;
    const int fg = lane >> 2, tig = lane & 3;
    const int pa[7] = {AH, AHS, AM, AN, AHS, AH, AG};
    const int prelu[7] = {0, 0, 0, 1, 1, 1, 1};

    for (int m0 = blockIdx.x * 64; m0 < NN; m0 += gridDim.x * 64) {
        float outv[32];
#pragma unroll
        for (int i = 0; i < 32; i++) outv[i] = 0.f;
        uint4 pf[8];
        {
            const uint4* s = (const uint4*)wbase;
#pragma unroll
            for (int i = 0; i < 8; i++) pf[i] = s[tid + i * 128];
        }

        for (int j = 0; j < nst; j++) {
            const float* h = (j == 0) ? h0p : (j == 1) ? h1p : (j == 2) ? h2p : (j == 3) ? h3p : h4p;
            int ldh = (j == 0) ? l0 : (j == 1) ? l1 : (j == 2) ? l2 : (j == 3) ? l3 : l4;
            const float* ssum = sums + (size_t)j * NSZ;
            const float* snrm = nrms + (size_t)j * NSZ;
            const __nv_bfloat16* wslot = wbase + (size_t)j * 7 * 8192;

            __syncthreads();  // prev slot done reading A tiles
#pragma unroll
            for (int i = 0; i < 8; i++) {
                int idx = tid + i * 128;
                int row = idx >> 4, cg = (idx & 15) * 4;
                int gm = m0 + row;
                float4 z = make_float4(0.f, 0.f, 0.f, 0.f);
                float4 hv = z, sv = z, nv = z, xv = z;
                float idg = 0.f;
                if (gm < NN) {
                    hv = *(const float4*)(h + (size_t)gm * ldh + cg);
                    sv = *(const float4*)(ssum + (size_t)gm * 64 + cg);
                    nv = *(const float4*)(snrm + (size_t)gm * 64 + cg);
                    xv = *(const float4*)(x0 + (size_t)gm * 64 + cg);
                    idg = invdeg[gm];
                }
                float4 hs = make_float4(hv.x + sv.x, hv.y + sv.y, hv.z + sv.z, hv.w + sv.w);
                float4 mv = make_float4(sv.x * idg, sv.y * idg, sv.z * idg, sv.w * idg);
                float4 gv = make_float4(0.9f * nv.x + 0.1f * xv.x, 0.9f * nv.y + 0.1f * xv.y,
                                        0.9f * nv.z + 0.1f * xv.z, 0.9f * nv.w + 0.1f * xv.w);
                int off = row * 144 + cg * 2;
                store_split4(smc + AH + off, smc + AH + 9216 + off, hv);
                store_split4(smc + AHS + off, smc + AHS + 9216 + off, hs);
                store_split4(smc + AM + off, smc + AM + 9216 + off, mv);
                store_split4(smc + AN + off, smc + AN + 9216 + off, nv);
                store_split4(smc + AG + off, smc + AG + 9216 + off, gv);
            }

            for (int p = 0; p < 7; p++) {
                __syncthreads();  // B free (prev panel done); A ready at p==0
#pragma unroll
                for (int i = 0; i < 8; i++) {
                    int u = tid + i * 128;
                    int r = u >> 3, c = u & 7;
                    int dst = BOF + ((r < 64) ? (r * 144 + c * 16) : (9216 + (r - 64) * 144 + c * 16));
                    *(uint4*)(smc + dst) = pf[i];
                }
                __syncthreads();
                if (p < 6 || j + 1 < nst) {
                    const uint4* s = (const uint4*)(wslot + (size_t)(p + 1) * 8192);
#pragma unroll
                    for (int i = 0; i < 8; i++) pf[i] = s[tid + i * 128];
                }
                float tc[32];
                float* dst = prelu[p] ? tc : outv;
                if (prelu[p]) {
#pragma unroll
                    for (int i = 0; i < 32; i++) tc[i] = 0.f;
                }
                const u32 At = sb + pa[p];
#pragma unroll
                for (int q = 0; q < 4; q++) {
                    u32 aAddr = At + (u32)((wrow + (lane & 7) + ((lane >> 3) & 1) * 8) * 144 + q * 32 + (lane >> 4) * 16);
                    u32 a0, a1, a2, a3, e0, e1, e2, e3;
                    ldsm4(a0, a1, a2, a3, aAddr);
                    ldsm4(e0, e1, e2, e3, aAddr + 9216);
                    u32 bRow = sb + BOF + (u32)((q * 16 + (lane & 15)) * 144);
#pragma unroll
                    for (int nb = 0; nb < 8; nb++) {
                        u32 b0, b1, c0, c1;
                        ldsm2t(b0, b1, bRow + nb * 16);
                        ldsm2t(c0, c1, bRow + nb * 16 + 9216);
                        mma16816(dst + nb * 4, a0, a1, a2, a3, b0, b1);
                        mma16816(dst + nb * 4, e0, e1, e2, e3, b0, b1);
                        mma16816(dst + nb * 4, a0, a1, a2, a3, c0, c1);
                    }
                }
                if (prelu[p]) {
#pragma unroll
                    for (int i = 0; i < 32; i++) outv[i] += fmaxf(tc[i], 0.f);
                }
            }
        }
        // fragment-layout direct store: rows (wrow+fg, wrow+fg+8), cols nb*8+tig*2
        int r0g = m0 + wrow + fg, r1g = r0g + 8;
#pragma unroll
        for (int nb = 0; nb < 8; nb++) {
            int c = nb * 8 + tig * 2;
            if (r0g < NN)
                *(float2*)(outp + (size_t)r0g * 256 + c) = make_float2(outv[nb * 4 + 0], outv[nb * 4 + 1]);
            if (r1g < NN)
                *(float2*)(outp + (size_t)r1g * 256 + c) = make_float2(outv[nb * 4 + 2], outv[nb * 4 + 3]);
        }
    }
}

__global__ void k_cls(const float* __restrict__ s1, const float* __restrict__ W,
                      const float* __restrict__ b, float* __restrict__ out) {
    int n = blockIdx.x;
    __shared__ float row[256];
    __shared__ float red[64];
    int tid = threadIdx.x;
    float ls = 0.f;
#pragma unroll
    for (int i = 0; i < 4; i++) {
        float v = s1[(size_t)n * 256 + tid + i * 64];
        row[tid + i * 64] = v;
        ls += v;
    }
    red[tid] = ls;
    __syncthreads();
    for (int off = 32; off > 0; off >>= 1) {
        if (tid < off) red[tid] += red[tid + off];
        __syncthreads();
    }
    float pooled = red[0] * (1.0f / 256.0f);
    if (tid < 40) {
        float acc = b[tid] + pooled * W[tid];
#pragma unroll 8
        for (int k = 0; k < 256; k++) acc += row[k] * W[(1 + k) * 40 + tid];
        out[(size_t)n * 40 + tid] = acc;
    }
}

static void bnrun(float* buf, int ncols, int ny, int dorelu, float* part, float* stats) {
    k_colfin<<<ncols, 256>>>(part, ny, stats);
    size_t total = (size_t)NN * ncols;
    k_bnapply<<<(int)((total + 255) / 256), 256>>>(buf, ncols, stats, dorelu);
}

extern "C" void kernel_launch(void* const* d_in, const int* in_sizes, int n_in,
                              void* d_out, int out_size) {
    const float* x = (const float*)d_in[0];
    const int* ei = (const int*)d_in[1];
    const float* alphas = (const float*)d_in[2];
    const float* stemW = (const float*)d_in[3];
    const float* preW = (const float*)d_in[4];
    const float* p0W0 = (const float*)d_in[5];
    const float* p1W0 = (const float*)d_in[6];
    const float* p0W1 = (const float*)d_in[7];
    const float* p1W1 = (const float*)d_in[8];
    const float* Wgcn = (const float*)d_in[9];
    const float* Wss = (const float*)d_in[10];
    const float* Wsn = (const float*)d_in[11];
    const float* Wgin = (const float*)d_in[12];
    const float* Wgc1 = (const float*)d_in[13];
    const float* Wgc2 = (const float*)d_in[14];
    const float* Wmlp = (const float*)d_in[15];
    const float* Wgcnii = (const float*)d_in[16];
    const float* clsW = (const float*)d_in[17];
    const float* clsb = (const float*)d_in[18];
    float* out = (float*)d_out;
    const int* srcI = ei;
    const int* dstI = ei + EE;

    float *stem, *x0p, *ap, *bp, *c0, *c1, *sums, *nrms, *wmix, *stats, *part;
    float *invdeg, *invsqrt, *ew;
    __nv_bfloat16* wbk;
    int *deg, *cursor, *rowptr, *eid, *srcs, *bsum;
    cudaGetSymbolAddress((void**)&stem, g_stem);
    cudaGetSymbolAddress((void**)&x0p, g_x0);
    cudaGetSymbolAddress((void**)&ap, g_a);
    cudaGetSymbolAddress((void**)&bp, g_b);
    cudaGetSymbolAddress((void**)&c0, g_cell0);
    cudaGetSymbolAddress((void**)&c1, g_cell1);
    cudaGetSymbolAddress((void**)&sums, g_sum);
    cudaGetSymbolAddress((void**)&nrms, g_nrm);
    cudaGetSymbolAddress((void**)&wbk, g_wbk);
    cudaGetSymbolAddress((void**)&wmix, g_wmix);
    cudaGetSymbolAddress((void**)&stats, g_stats);
    cudaGetSymbolAddress((void**)&part, g_part);
    cudaGetSymbolAddress((void**)&invdeg, g_invdeg);
    cudaGetSymbolAddress((void**)&invsqrt, g_invsqrt);
    cudaGetSymbolAddress((void**)&ew, g_ew);
    cudaGetSymbolAddress((void**)&deg, g_deg);
    cudaGetSymbolAddress((void**)&cursor, g_cursor);
    cudaGetSymbolAddress((void**)&rowptr, g_rowptr);
    cudaGetSymbolAddress((void**)&eid, g_eid);
    cudaGetSymbolAddress((void**)&srcs, g_srcs);
    cudaGetSymbolAddress((void**)&bsum, g_bsum);

    cudaFuncSetAttribute(k_step, cudaFuncAttributeMaxDynamicSharedMemorySize, STEP_SMEM);

    k_zero2<<<(NN + 255) / 256, 256>>>(deg, cursor);
    k_deg<<<(EE + 255) / 256, 256>>>(dstI, deg);
    k_degfin<<<(NN + 255) / 256, 256>>>(deg, invdeg, invsqrt);
    k_scan1<<<SCAN_B, 128>>>(deg, rowptr, bsum);
    k_scan2<<<1, 512>>>(bsum);
    k_scan3<<<(NN + 255) / 256, 256>>>(rowptr, bsum);
    k_scatter<<<(EE + 255) / 256, 256>>>(dstI, rowptr, cursor, eid);
    k_sortfill<<<(NN + 127) / 128, 128>>>(rowptr, eid, srcI, invsqrt, srcs, ew);

    k_softmax<<<1, 16>>>(alphas, wmix);
    k_bake<<<28, 256>>>(wmix, Wgcn, Wss, Wsn, Wgin, Wgc1, Wgc2, Wmlp, Wgcnii, wbk);

    k_gemm<<<dim3(MT64, 3), 256>>>(x, 128, stemW, 192, stem, 128, part);
    bnrun(stem, 192, 3, 0, part, stats);
    k_gemm<<<dim3(MT64, 1), 256>>>(x, 128, preW, 64, x0p, 128, part);
    bnrun(x0p, 64, 1, 1, part, stats);

    const int aggBlocks = (NN * 32 + 255) / 256;
    for (int ci = 0; ci < 2; ci++) {
        const float* s0 = stem; int k0 = 192;
        const float* s1 = (ci == 0) ? stem : c0;
        int k1 = (ci == 0) ? 192 : 256;
        const float* pW0 = (ci == 0) ? p0W0 : p0W1;
        const float* pW1 = (ci == 0) ? p1W0 : p1W1;
        float* cell = (ci == 0) ? c0 : c1;

        k_gemm<<<dim3(MT64, 1), 256>>>(s0, k0, pW0, 64, ap, k0, part);
        bnrun(ap, 64, 1, 1, part, stats);
        k_gemm<<<dim3(MT64, 1), 256>>>(s1, k1, pW1, 64, bp, k1, part);
        bnrun(bp, 64, 1, 1, part, stats);

        const float* sp[5] = {ap, bp, cell, cell + 64, cell + 128};
        const int sl[5] = {64, 64, 256, 256, 256};
        k_agg2<<<aggBlocks, 256>>>(sp[0], sl[0], sp[1], sl[1], rowptr, srcs, ew, sums, nrms);

        int ej0 = 0;
        for (int t = 0; t < 4; t++) {
            const __nv_bfloat16* wb = wbk + (size_t)(ci * 14 + ej0) * 7 * 8192;
            k_step<<<PGRID, 128, STEP_SMEM>>>(sp[0], sp[1], sp[2], sp[3], sp[4],
                                              sl[0], sl[1], sl[2], sl[3], sl[4],
                                              sums, nrms, x0p, invdeg, wb, t + 2, cell + t * 64);
            ej0 += t + 2;
            if (t < 3) {
                int ns = t + 2;
                k_agg<<<aggBlocks, 256>>>(sp[ns], sl[ns], rowptr, srcs, ew,
                                          sums + (size_t)ns * NSZ, nrms + (size_t)ns * NSZ);
            }
        }
    }
    k_cls<<<NN, 64>>>(c1, clsW, clsb, out);
}